// round 10
// baseline (speedup 1.0000x reference)
#include <cuda_runtime.h>
#include <math.h>

#define HDIM 4096
#define NEXP 8
#define H4   (HDIM / 4)   // float4 (16B) units per token row = 1024

// Packed dual-fp32 FMA (sm_103a): acc.{lo,hi} += a.{lo,hi} * b.{lo,hi}
static __device__ __forceinline__ void ffma2(unsigned long long &acc,
                                             unsigned long long a,
                                             unsigned long long b) {
    asm("fma.rn.f32x2 %0, %1, %2, %0;" : "+l"(acc) : "l"(a), "l"(b));
}

// One warp computes logits for T consecutive tokens.
// Lane l covers k-positions {l*4 + 128*i}; x loaded as 16B vectors straight
// from GMEM (coalesced 512B per warp per token), W read from SMEM (conflict-
// free consecutive 16B per lane). Accumulators are f32x2 pairs over adjacent
// k (even/odd), combined at the end — no repacking needed.
template <int T>
static __device__ __forceinline__ void process_tokens(
    const float* __restrict__ x,
    const ulonglong2* __restrict__ wsm,   // shared: [NEXP][H4] as 16B vectors
    int tok0, int n_tokens,
    float* __restrict__ out, int lane)
{
    unsigned long long acc[T][NEXP];
#pragma unroll
    for (int t = 0; t < T; ++t)
#pragma unroll
        for (int e = 0; e < NEXP; ++e) acc[t][e] = 0ULL;

    const ulonglong2* xp = reinterpret_cast<const ulonglong2*>(x)
                         + (size_t)tok0 * H4 + lane;
    const ulonglong2* wp = wsm + lane;

#pragma unroll 2
    for (int i = 0; i < H4 / 32; ++i) {          // 32 k-steps of 128 floats
        ulonglong2 xv[T];
#pragma unroll
        for (int t = 0; t < T; ++t)
            xv[t] = xp[(size_t)t * H4 + i * 32];
#pragma unroll
        for (int e = 0; e < NEXP; ++e) {
            ulonglong2 wv = wp[e * H4 + i * 32];
#pragma unroll
            for (int t = 0; t < T; ++t) {
                ffma2(acc[t][e], xv[t].x, wv.x);
                ffma2(acc[t][e], xv[t].y, wv.y);
            }
        }
    }

    float* w_out = out;                              // routing_weights [N,2]
    float* e_out = out + 2 * (size_t)n_tokens;       // selected_experts [N,2]
    float* l_out = out + 4 * (size_t)n_tokens;       // router_logits [N,8]

#pragma unroll
    for (int t = 0; t < T; ++t) {
        float p[NEXP];
#pragma unroll
        for (int e = 0; e < NEXP; ++e) {
            unsigned long long a = acc[t][e];
            p[e] = __int_as_float((int)(unsigned)a)
                 + __int_as_float((int)(a >> 32));
        }
        // full-warp butterfly reduction: every lane ends with all 8 logits
#pragma unroll
        for (int off = 16; off > 0; off >>= 1)
#pragma unroll
            for (int e = 0; e < NEXP; ++e)
                p[e] += __shfl_xor_sync(0xffffffffu, p[e], off);

        if (lane == 0) {
            int tok = tok0 + t;
            // top-2 (lowest index wins ties, matching jax.lax.top_k)
            float b0 = p[0]; int i0 = 0;
#pragma unroll
            for (int e = 1; e < NEXP; ++e)
                if (p[e] > b0) { b0 = p[e]; i0 = e; }
            float b1 = -3.402823466e38f; int i1 = 0;
#pragma unroll
            for (int e = 0; e < NEXP; ++e)
                if (e != i0 && p[e] > b1) { b1 = p[e]; i1 = e; }
            // softmax over the two gathered logits (b0 >= b1)
            float d = expf(b1 - b0);
            float r = 1.0f / (1.0f + d);
            *reinterpret_cast<float2*>(w_out + (size_t)tok * 2) =
                make_float2(r, d * r);
            *reinterpret_cast<float2*>(e_out + (size_t)tok * 2) =
                make_float2((float)i0, (float)i1);
            *reinterpret_cast<float4*>(l_out + (size_t)tok * 8) =
                make_float4(p[0], p[1], p[2], p[3]);
            *reinterpret_cast<float4*>(l_out + (size_t)tok * 8 + 4) =
                make_float4(p[4], p[5], p[6], p[7]);
        }
    }
}

__global__ void __launch_bounds__(512, 1)
topk_router_kernel(const float* __restrict__ x, const float* __restrict__ W,
                   float* __restrict__ out, int n_tokens, int total_warps)
{
    extern __shared__ float wsm_f[];
    // Stage all of W (8 x 4096 fp32 = 128 KB) into SMEM, coalesced.
    {
        const float4* Wg = reinterpret_cast<const float4*>(W);
        float4*       Ws = reinterpret_cast<float4*>(wsm_f);
        for (int i = threadIdx.x; i < NEXP * H4; i += blockDim.x)
            Ws[i] = Wg[i];
    }
    __syncthreads();

    const int lane = threadIdx.x & 31;
    const int gw   = blockIdx.x * (blockDim.x >> 5) + (threadIdx.x >> 5);

    // Near-perfectly balanced token ranges (6 or 7 tokens per warp).
    int t_begin = (int)(((long long)gw       * n_tokens) / total_warps);
    int t_end   = (int)(((long long)(gw + 1) * n_tokens) / total_warps);

    const ulonglong2* wsm = reinterpret_cast<const ulonglong2*>(wsm_f);

    int t = t_begin;
    while (t_end - t >= 4) {
        process_tokens<4>(x, wsm, t, n_tokens, out, lane);
        t += 4;
    }
    int rem = t_end - t;
    if (rem == 3)      process_tokens<3>(x, wsm, t, n_tokens, out, lane);
    else if (rem == 2) process_tokens<2>(x, wsm, t, n_tokens, out, lane);
    else if (rem == 1) process_tokens<1>(x, wsm, t, n_tokens, out, lane);
}

extern "C" void kernel_launch(void* const* d_in, const int* in_sizes, int n_in,
                              void* d_out, int out_size)
{
    const float* x = (const float*)d_in[0];   // hidden_states [4,4096,4096] f32
    const float* W = (const float*)d_in[1];   // W [8,4096] f32
    float* out = (float*)d_out;

    const int n_tokens = in_sizes[0] / HDIM;  // 16384

    int sms = 148;
    cudaDeviceGetAttribute(&sms, cudaDevAttrMultiProcessorCount, 0);

    const int threads = 512;
    const size_t smem = (size_t)NEXP * HDIM * sizeof(float);  // 128 KB
    cudaFuncSetAttribute(topk_router_kernel,
                         cudaFuncAttributeMaxDynamicSharedMemorySize,
                         (int)smem);

    const int blocks = sms;                    // 1 persistent block per SM
    const int total_warps = blocks * (threads / 32);

    topk_router_kernel<<<blocks, threads, smem>>>(x, W, out,
                                                  n_tokens, total_warps);
}

// round 11
// speedup vs baseline: 1.0065x; 1.0065x over previous
#include <cuda_runtime.h>
#include <math.h>

#define HDIM 4096
#define NEXP 8
#define H4   (HDIM / 4)   // float4 (16B) units per token row = 1024

// Packed dual-fp32 FMA (sm_103a): acc.{lo,hi} += a.{lo,hi} * b.{lo,hi}
static __device__ __forceinline__ void ffma2(unsigned long long &acc,
                                             unsigned long long a,
                                             unsigned long long b) {
    asm("fma.rn.f32x2 %0, %1, %2, %0;" : "+l"(acc) : "l"(a), "l"(b));
}

// One warp computes logits for T consecutive tokens.
// Lane l covers k-positions {l*4 + 128*i}; x loaded as 16B vectors straight
// from GMEM (coalesced 512B per warp per token), W read from SMEM (conflict-
// free consecutive 16B per lane). Accumulators are f32x2 pairs over adjacent
// k (even/odd), combined at the end — no repacking needed.
template <int T>
static __device__ __forceinline__ void process_tokens(
    const float* __restrict__ x,
    const ulonglong2* __restrict__ wsm,   // shared: [NEXP][H4] as 16B vectors
    int tok0, int n_tokens,
    float* __restrict__ out, int lane)
{
    unsigned long long acc[T][NEXP];
#pragma unroll
    for (int t = 0; t < T; ++t)
#pragma unroll
        for (int e = 0; e < NEXP; ++e) acc[t][e] = 0ULL;

    const ulonglong2* xp = reinterpret_cast<const ulonglong2*>(x)
                         + (size_t)tok0 * H4 + lane;
    const ulonglong2* wp = wsm + lane;

#pragma unroll 2
    for (int i = 0; i < H4 / 32; ++i) {          // 32 k-steps of 128 floats
        ulonglong2 xv[T];
#pragma unroll
        for (int t = 0; t < T; ++t)
            xv[t] = xp[(size_t)t * H4 + i * 32];
#pragma unroll
        for (int e = 0; e < NEXP; ++e) {
            ulonglong2 wv = wp[e * H4 + i * 32];
#pragma unroll
            for (int t = 0; t < T; ++t) {
                ffma2(acc[t][e], xv[t].x, wv.x);
                ffma2(acc[t][e], xv[t].y, wv.y);
            }
        }
    }

    float* w_out = out;                              // routing_weights [N,2]
    float* e_out = out + 2 * (size_t)n_tokens;       // selected_experts [N,2]
    float* l_out = out + 4 * (size_t)n_tokens;       // router_logits [N,8]

#pragma unroll
    for (int t = 0; t < T; ++t) {
        float p[NEXP];
#pragma unroll
        for (int e = 0; e < NEXP; ++e) {
            unsigned long long a = acc[t][e];
            p[e] = __int_as_float((int)(unsigned)a)
                 + __int_as_float((int)(a >> 32));
        }
        // full-warp butterfly reduction: every lane ends with all 8 logits
#pragma unroll
        for (int off = 16; off > 0; off >>= 1)
#pragma unroll
            for (int e = 0; e < NEXP; ++e)
                p[e] += __shfl_xor_sync(0xffffffffu, p[e], off);

        if (lane == 0) {
            int tok = tok0 + t;
            // top-2 (lowest index wins ties, matching jax.lax.top_k)
            float b0 = p[0]; int i0 = 0;
#pragma unroll
            for (int e = 1; e < NEXP; ++e)
                if (p[e] > b0) { b0 = p[e]; i0 = e; }
            float b1 = -3.402823466e38f; int i1 = 0;
#pragma unroll
            for (int e = 0; e < NEXP; ++e)
                if (e != i0 && p[e] > b1) { b1 = p[e]; i1 = e; }
            // softmax over the two gathered logits (b0 >= b1)
            float d = expf(b1 - b0);
            float r = 1.0f / (1.0f + d);
            *reinterpret_cast<float2*>(w_out + (size_t)tok * 2) =
                make_float2(r, d * r);
            *reinterpret_cast<float2*>(e_out + (size_t)tok * 2) =
                make_float2((float)i0, (float)i1);
            *reinterpret_cast<float4*>(l_out + (size_t)tok * 8) =
                make_float4(p[0], p[1], p[2], p[3]);
            *reinterpret_cast<float4*>(l_out + (size_t)tok * 8 + 4) =
                make_float4(p[4], p[5], p[6], p[7]);
        }
    }
}

__global__ void __launch_bounds__(512, 1)
topk_router_kernel(const float* __restrict__ x, const float* __restrict__ W,
                   float* __restrict__ out, int n_tokens, int total_warps)
{
    extern __shared__ float wsm_f[];
    // Stage all of W (8 x 4096 fp32 = 128 KB) into SMEM, coalesced.
    {
        const float4* Wg = reinterpret_cast<const float4*>(W);
        float4*       Ws = reinterpret_cast<float4*>(wsm_f);
        for (int i = threadIdx.x; i < NEXP * H4; i += blockDim.x)
            Ws[i] = Wg[i];
    }
    __syncthreads();

    const int lane = threadIdx.x & 31;
    const int gw   = blockIdx.x * (blockDim.x >> 5) + (threadIdx.x >> 5);

    // Near-perfectly balanced token ranges (6 or 7 tokens per warp).
    int t_begin = (int)(((long long)gw       * n_tokens) / total_warps);
    int t_end   = (int)(((long long)(gw + 1) * n_tokens) / total_warps);

    const ulonglong2* wsm = reinterpret_cast<const ulonglong2*>(wsm_f);

    int t = t_begin;
    while (t_end - t >= 4) {
        process_tokens<4>(x, wsm, t, n_tokens, out, lane);
        t += 4;
    }
    int rem = t_end - t;
    if (rem == 3)      process_tokens<3>(x, wsm, t, n_tokens, out, lane);
    else if (rem == 2) process_tokens<2>(x, wsm, t, n_tokens, out, lane);
    else if (rem == 1) process_tokens<1>(x, wsm, t, n_tokens, out, lane);
}

extern "C" void kernel_launch(void* const* d_in, const int* in_sizes, int n_in,
                              void* d_out, int out_size)
{
    const float* x = (const float*)d_in[0];   // hidden_states [4,4096,4096] f32
    const float* W = (const float*)d_in[1];   // W [8,4096] f32
    float* out = (float*)d_out;

    const int n_tokens = in_sizes[0] / HDIM;  // 16384

    int sms = 148;
    cudaDeviceGetAttribute(&sms, cudaDevAttrMultiProcessorCount, 0);

    const int threads = 512;
    const size_t smem = (size_t)NEXP * HDIM * sizeof(float);  // 128 KB
    cudaFuncSetAttribute(topk_router_kernel,
                         cudaFuncAttributeMaxDynamicSharedMemorySize,
                         (int)smem);

    const int blocks = sms;                    // 1 persistent block per SM
    const int total_warps = blocks * (threads / 32);

    topk_router_kernel<<<blocks, threads, smem>>>(x, W, out,
                                                  n_tokens, total_warps);
}

// round 12
// speedup vs baseline: 1.0070x; 1.0005x over previous
#include <cuda_runtime.h>
#include <math.h>

#define HDIM 4096
#define NEXP 8
#define H4   (HDIM / 4)   // float4 (16B) units per token row = 1024

// Packed dual-fp32 FMA (sm_103a): acc.{lo,hi} += a.{lo,hi} * b.{lo,hi}
static __device__ __forceinline__ void ffma2(unsigned long long &acc,
                                             unsigned long long a,
                                             unsigned long long b) {
    asm("fma.rn.f32x2 %0, %1, %2, %0;" : "+l"(acc) : "l"(a), "l"(b));
}

// One warp computes logits for T consecutive tokens.
// Lane l covers k-positions {l*4 + 128*i}; x loaded as 16B vectors straight
// from GMEM (coalesced 512B per warp per token), W read from SMEM (conflict-
// free consecutive 16B per lane). Accumulators are f32x2 pairs over adjacent
// k (even/odd), combined at the end — no repacking needed.
template <int T>
static __device__ __forceinline__ void process_tokens(
    const float* __restrict__ x,
    const ulonglong2* __restrict__ wsm,   // shared: [NEXP][H4] as 16B vectors
    int tok0, int n_tokens,
    float* __restrict__ out, int lane)
{
    unsigned long long acc[T][NEXP];
#pragma unroll
    for (int t = 0; t < T; ++t)
#pragma unroll
        for (int e = 0; e < NEXP; ++e) acc[t][e] = 0ULL;

    const ulonglong2* xp = reinterpret_cast<const ulonglong2*>(x)
                         + (size_t)tok0 * H4 + lane;
    const ulonglong2* wp = wsm + lane;

#pragma unroll 2
    for (int i = 0; i < H4 / 32; ++i) {          // 32 k-steps of 128 floats
        ulonglong2 xv[T];
#pragma unroll
        for (int t = 0; t < T; ++t)
            xv[t] = xp[(size_t)t * H4 + i * 32];
#pragma unroll
        for (int e = 0; e < NEXP; ++e) {
            ulonglong2 wv = wp[e * H4 + i * 32];
#pragma unroll
            for (int t = 0; t < T; ++t) {
                ffma2(acc[t][e], xv[t].x, wv.x);
                ffma2(acc[t][e], xv[t].y, wv.y);
            }
        }
    }

    float* w_out = out;                              // routing_weights [N,2]
    float* e_out = out + 2 * (size_t)n_tokens;       // selected_experts [N,2]
    float* l_out = out + 4 * (size_t)n_tokens;       // router_logits [N,8]

#pragma unroll
    for (int t = 0; t < T; ++t) {
        float p[NEXP];
#pragma unroll
        for (int e = 0; e < NEXP; ++e) {
            unsigned long long a = acc[t][e];
            p[e] = __int_as_float((int)(unsigned)a)
                 + __int_as_float((int)(a >> 32));
        }
        // full-warp butterfly reduction: every lane ends with all 8 logits
#pragma unroll
        for (int off = 16; off > 0; off >>= 1)
#pragma unroll
            for (int e = 0; e < NEXP; ++e)
                p[e] += __shfl_xor_sync(0xffffffffu, p[e], off);

        if (lane == 0) {
            int tok = tok0 + t;
            // top-2 (lowest index wins ties, matching jax.lax.top_k)
            float b0 = p[0]; int i0 = 0;
#pragma unroll
            for (int e = 1; e < NEXP; ++e)
                if (p[e] > b0) { b0 = p[e]; i0 = e; }
            float b1 = -3.402823466e38f; int i1 = 0;
#pragma unroll
            for (int e = 0; e < NEXP; ++e)
                if (e != i0 && p[e] > b1) { b1 = p[e]; i1 = e; }
            // softmax over the two gathered logits (b0 >= b1)
            float d = expf(b1 - b0);
            float r = 1.0f / (1.0f + d);
            *reinterpret_cast<float2*>(w_out + (size_t)tok * 2) =
                make_float2(r, d * r);
            *reinterpret_cast<float2*>(e_out + (size_t)tok * 2) =
                make_float2((float)i0, (float)i1);
            *reinterpret_cast<float4*>(l_out + (size_t)tok * 8) =
                make_float4(p[0], p[1], p[2], p[3]);
            *reinterpret_cast<float4*>(l_out + (size_t)tok * 8 + 4) =
                make_float4(p[4], p[5], p[6], p[7]);
        }
    }
}

__global__ void __launch_bounds__(512, 1)
topk_router_kernel(const float* __restrict__ x, const float* __restrict__ W,
                   float* __restrict__ out, int n_tokens, int total_warps)
{
    extern __shared__ float wsm_f[];
    // Stage all of W (8 x 4096 fp32 = 128 KB) into SMEM, coalesced.
    {
        const float4* Wg = reinterpret_cast<const float4*>(W);
        float4*       Ws = reinterpret_cast<float4*>(wsm_f);
        for (int i = threadIdx.x; i < NEXP * H4; i += blockDim.x)
            Ws[i] = Wg[i];
    }
    __syncthreads();

    const int lane = threadIdx.x & 31;
    const int gw   = blockIdx.x * (blockDim.x >> 5) + (threadIdx.x >> 5);

    // Near-perfectly balanced token ranges (6 or 7 tokens per warp).
    int t_begin = (int)(((long long)gw       * n_tokens) / total_warps);
    int t_end   = (int)(((long long)(gw + 1) * n_tokens) / total_warps);

    const ulonglong2* wsm = reinterpret_cast<const ulonglong2*>(wsm_f);

    int t = t_begin;
    while (t_end - t >= 4) {
        process_tokens<4>(x, wsm, t, n_tokens, out, lane);
        t += 4;
    }
    int rem = t_end - t;
    if (rem == 3)      process_tokens<3>(x, wsm, t, n_tokens, out, lane);
    else if (rem == 2) process_tokens<2>(x, wsm, t, n_tokens, out, lane);
    else if (rem == 1) process_tokens<1>(x, wsm, t, n_tokens, out, lane);
}

extern "C" void kernel_launch(void* const* d_in, const int* in_sizes, int n_in,
                              void* d_out, int out_size)
{
    const float* x = (const float*)d_in[0];   // hidden_states [4,4096,4096] f32
    const float* W = (const float*)d_in[1];   // W [8,4096] f32
    float* out = (float*)d_out;

    const int n_tokens = in_sizes[0] / HDIM;  // 16384

    int sms = 148;
    cudaDeviceGetAttribute(&sms, cudaDevAttrMultiProcessorCount, 0);

    const int threads = 512;
    const size_t smem = (size_t)NEXP * HDIM * sizeof(float);  // 128 KB
    cudaFuncSetAttribute(topk_router_kernel,
                         cudaFuncAttributeMaxDynamicSharedMemorySize,
                         (int)smem);

    const int blocks = sms;                    // 1 persistent block per SM
    const int total_warps = blocks * (threads / 32);

    topk_router_kernel<<<blocks, threads, smem>>>(x, W, out,
                                                  n_tokens, total_warps);
}

// round 13
// speedup vs baseline: 1.0114x; 1.0043x over previous
#include <cuda_runtime.h>
#include <math.h>

#define HDIM 4096
#define NEXP 8
#define H4   (HDIM / 4)   // float4 (16B) units per token row = 1024

// Packed dual-fp32 FMA (sm_103a): acc.{lo,hi} += a.{lo,hi} * b.{lo,hi}
static __device__ __forceinline__ void ffma2(unsigned long long &acc,
                                             unsigned long long a,
                                             unsigned long long b) {
    asm("fma.rn.f32x2 %0, %1, %2, %0;" : "+l"(acc) : "l"(a), "l"(b));
}

// One warp computes logits for T consecutive tokens.
// Lane l covers k-positions {l*4 + 128*i}; x loaded as 16B vectors straight
// from GMEM (coalesced 512B per warp per token), W read from SMEM (conflict-
// free consecutive 16B per lane). Accumulators are f32x2 pairs over adjacent
// k (even/odd), combined at the end — no repacking needed.
template <int T>
static __device__ __forceinline__ void process_tokens(
    const float* __restrict__ x,
    const ulonglong2* __restrict__ wsm,   // shared: [NEXP][H4] as 16B vectors
    int tok0, int n_tokens,
    float* __restrict__ out, int lane)
{
    unsigned long long acc[T][NEXP];
#pragma unroll
    for (int t = 0; t < T; ++t)
#pragma unroll
        for (int e = 0; e < NEXP; ++e) acc[t][e] = 0ULL;

    const ulonglong2* xp = reinterpret_cast<const ulonglong2*>(x)
                         + (size_t)tok0 * H4 + lane;
    const ulonglong2* wp = wsm + lane;

#pragma unroll 2
    for (int i = 0; i < H4 / 32; ++i) {          // 32 k-steps of 128 floats
        ulonglong2 xv[T];
#pragma unroll
        for (int t = 0; t < T; ++t)
            xv[t] = xp[(size_t)t * H4 + i * 32];
#pragma unroll
        for (int e = 0; e < NEXP; ++e) {
            ulonglong2 wv = wp[e * H4 + i * 32];
#pragma unroll
            for (int t = 0; t < T; ++t) {
                ffma2(acc[t][e], xv[t].x, wv.x);
                ffma2(acc[t][e], xv[t].y, wv.y);
            }
        }
    }

    float* w_out = out;                              // routing_weights [N,2]
    float* e_out = out + 2 * (size_t)n_tokens;       // selected_experts [N,2]
    float* l_out = out + 4 * (size_t)n_tokens;       // router_logits [N,8]

#pragma unroll
    for (int t = 0; t < T; ++t) {
        float p[NEXP];
#pragma unroll
        for (int e = 0; e < NEXP; ++e) {
            unsigned long long a = acc[t][e];
            p[e] = __int_as_float((int)(unsigned)a)
                 + __int_as_float((int)(a >> 32));
        }
        // full-warp butterfly reduction: every lane ends with all 8 logits
#pragma unroll
        for (int off = 16; off > 0; off >>= 1)
#pragma unroll
            for (int e = 0; e < NEXP; ++e)
                p[e] += __shfl_xor_sync(0xffffffffu, p[e], off);

        if (lane == 0) {
            int tok = tok0 + t;
            // top-2 (lowest index wins ties, matching jax.lax.top_k)
            float b0 = p[0]; int i0 = 0;
#pragma unroll
            for (int e = 1; e < NEXP; ++e)
                if (p[e] > b0) { b0 = p[e]; i0 = e; }
            float b1 = -3.402823466e38f; int i1 = 0;
#pragma unroll
            for (int e = 0; e < NEXP; ++e)
                if (e != i0 && p[e] > b1) { b1 = p[e]; i1 = e; }
            // softmax over the two gathered logits (b0 >= b1)
            float d = expf(b1 - b0);
            float r = 1.0f / (1.0f + d);
            *reinterpret_cast<float2*>(w_out + (size_t)tok * 2) =
                make_float2(r, d * r);
            *reinterpret_cast<float2*>(e_out + (size_t)tok * 2) =
                make_float2((float)i0, (float)i1);
            *reinterpret_cast<float4*>(l_out + (size_t)tok * 8) =
                make_float4(p[0], p[1], p[2], p[3]);
            *reinterpret_cast<float4*>(l_out + (size_t)tok * 8 + 4) =
                make_float4(p[4], p[5], p[6], p[7]);
        }
    }
}

__global__ void __launch_bounds__(512, 1)
topk_router_kernel(const float* __restrict__ x, const float* __restrict__ W,
                   float* __restrict__ out, int n_tokens, int total_warps)
{
    extern __shared__ float wsm_f[];
    // Stage all of W (8 x 4096 fp32 = 128 KB) into SMEM, coalesced.
    {
        const float4* Wg = reinterpret_cast<const float4*>(W);
        float4*       Ws = reinterpret_cast<float4*>(wsm_f);
        for (int i = threadIdx.x; i < NEXP * H4; i += blockDim.x)
            Ws[i] = Wg[i];
    }
    __syncthreads();

    const int lane = threadIdx.x & 31;
    const int gw   = blockIdx.x * (blockDim.x >> 5) + (threadIdx.x >> 5);

    // Near-perfectly balanced token ranges (6 or 7 tokens per warp).
    int t_begin = (int)(((long long)gw       * n_tokens) / total_warps);
    int t_end   = (int)(((long long)(gw + 1) * n_tokens) / total_warps);

    const ulonglong2* wsm = reinterpret_cast<const ulonglong2*>(wsm_f);

    int t = t_begin;
    while (t_end - t >= 4) {
        process_tokens<4>(x, wsm, t, n_tokens, out, lane);
        t += 4;
    }
    int rem = t_end - t;
    if (rem == 3)      process_tokens<3>(x, wsm, t, n_tokens, out, lane);
    else if (rem == 2) process_tokens<2>(x, wsm, t, n_tokens, out, lane);
    else if (rem == 1) process_tokens<1>(x, wsm, t, n_tokens, out, lane);
}

extern "C" void kernel_launch(void* const* d_in, const int* in_sizes, int n_in,
                              void* d_out, int out_size)
{
    const float* x = (const float*)d_in[0];   // hidden_states [4,4096,4096] f32
    const float* W = (const float*)d_in[1];   // W [8,4096] f32
    float* out = (float*)d_out;

    const int n_tokens = in_sizes[0] / HDIM;  // 16384

    int sms = 148;
    cudaDeviceGetAttribute(&sms, cudaDevAttrMultiProcessorCount, 0);

    const int threads = 512;
    const size_t smem = (size_t)NEXP * HDIM * sizeof(float);  // 128 KB
    cudaFuncSetAttribute(topk_router_kernel,
                         cudaFuncAttributeMaxDynamicSharedMemorySize,
                         (int)smem);

    const int blocks = sms;                    // 1 persistent block per SM
    const int total_warps = blocks * (threads / 32);

    topk_router_kernel<<<blocks, threads, smem>>>(x, W, out,
                                                  n_tokens, total_warps);
}